// round 2
// baseline (speedup 1.0000x reference)
#include <cuda_runtime.h>
#include <cuda_bf16.h>

#define N_NODES 50000
#define N_EDGES 250000
#define D_IN    768
#define D_HID   256
// y layout: [N_NODES][512], cols 0..255 = y_l = x@W1_l^T, cols 256..511 = y_r = x@W1_r^T

__device__ float g_y[(size_t)N_NODES * 512];
__device__ float g_agg1[(size_t)N_NODES * 256];
__device__ float g_h[(size_t)N_NODES * 256];
__device__ float g_cnt[N_NODES];
__device__ float g_z[(size_t)N_NODES * 4];   // z_l0,z_l1,z_r0,z_r1 per node
__device__ float g_agg2[(size_t)N_NODES * 2];

// ---------------------------------------------------------------------------
// zero scratch accumulators (must run every launch; graph replays)
// ---------------------------------------------------------------------------
__global__ void zero_kernel() {
    int t = blockIdx.x * 256 + threadIdx.x;
    if (t < N_NODES * 64) reinterpret_cast<float4*>(g_agg1)[t] = make_float4(0.f, 0.f, 0.f, 0.f);
    if (t < N_NODES)      g_cnt[t] = 0.f;
    if (t < N_NODES * 2)  g_agg2[t] = 0.f;
}

// ---------------------------------------------------------------------------
// GEMM1: g_y[M,512] = x[M,768] @ W^T, W = W1_l (cols 0..255) / W1_r (cols 256..511)
// 128x128 block tile, BK=16, 8x8 per thread, 256 threads
// ---------------------------------------------------------------------------
__global__ void __launch_bounds__(256) gemm1_kernel(
    const float* __restrict__ A,
    const float* __restrict__ Bl,
    const float* __restrict__ Br,
    int M)
{
    const int K = D_IN;
    __shared__ float As[16][132];
    __shared__ float Bs[16][132];

    const int tid   = threadIdx.x;
    const int mbase = blockIdx.x * 128;
    const int by    = blockIdx.y;                 // 0..3
    const float* Bp = (by < 2) ? Bl : Br;
    const int nb    = (by & 1) * 128;             // row offset inside W
    const int cb    = by * 128;                   // col offset inside C (stride 512)

    const int lrow = tid >> 2;                    // 0..63
    const int lc4  = tid & 3;                     // 0..3 (float4 column within BK=16)

    float acc[8][8];
#pragma unroll
    for (int i = 0; i < 8; i++)
#pragma unroll
        for (int j = 0; j < 8; j++) acc[i][j] = 0.f;

    const int ty = tid >> 4, tx = tid & 15;

#pragma unroll 1
    for (int k0 = 0; k0 < K; k0 += 16) {
#pragma unroll
        for (int r = 0; r < 2; r++) {
            int row = lrow + r * 64;
            int gm  = mbase + row;
            float4 v = make_float4(0.f, 0.f, 0.f, 0.f);
            if (gm < M)
                v = *reinterpret_cast<const float4*>(A + (size_t)gm * K + k0 + lc4 * 4);
            As[lc4 * 4 + 0][row] = v.x;
            As[lc4 * 4 + 1][row] = v.y;
            As[lc4 * 4 + 2][row] = v.z;
            As[lc4 * 4 + 3][row] = v.w;

            float4 w = *reinterpret_cast<const float4*>(Bp + (size_t)(nb + row) * K + k0 + lc4 * 4);
            Bs[lc4 * 4 + 0][row] = w.x;
            Bs[lc4 * 4 + 1][row] = w.y;
            Bs[lc4 * 4 + 2][row] = w.z;
            Bs[lc4 * 4 + 3][row] = w.w;
        }
        __syncthreads();

#pragma unroll
        for (int k = 0; k < 16; k++) {
            float a[8], b[8];
            *reinterpret_cast<float4*>(&a[0]) = *reinterpret_cast<const float4*>(&As[k][ty * 8]);
            *reinterpret_cast<float4*>(&a[4]) = *reinterpret_cast<const float4*>(&As[k][ty * 8 + 4]);
            *reinterpret_cast<float4*>(&b[0]) = *reinterpret_cast<const float4*>(&Bs[k][tx * 8]);
            *reinterpret_cast<float4*>(&b[4]) = *reinterpret_cast<const float4*>(&Bs[k][tx * 8 + 4]);
#pragma unroll
            for (int i = 0; i < 8; i++)
#pragma unroll
                for (int j = 0; j < 8; j++)
                    acc[i][j] = fmaf(a[i], b[j], acc[i][j]);
        }
        __syncthreads();
    }

#pragma unroll
    for (int i = 0; i < 8; i++) {
        int gm = mbase + ty * 8 + i;
        if (gm < M) {
            float4 v0 = make_float4(acc[i][0], acc[i][1], acc[i][2], acc[i][3]);
            float4 v1 = make_float4(acc[i][4], acc[i][5], acc[i][6], acc[i][7]);
            float* cp = g_y + (size_t)gm * 512 + cb + tx * 8;
            *reinterpret_cast<float4*>(cp)     = v0;
            *reinterpret_cast<float4*>(cp + 4) = v1;
        }
    }
}

// ---------------------------------------------------------------------------
// Edge scatter of y_l (256 floats/edge) with vectorized global reductions.
// 64 float4-chunks per edge; also accumulates the in-degree count.
// edge_index is int32 (JAX default x64-disabled downcasts int64 -> int32).
// ---------------------------------------------------------------------------
__global__ void scatter1_kernel(const int* __restrict__ ei) {
    int t = blockIdx.x * 256 + threadIdx.x;
    int e = t >> 6;
    int c = t & 63;
    if (e >= N_EDGES) return;
    int src = ei[e];
    int dst = ei[N_EDGES + e];

    float4 v = *reinterpret_cast<const float4*>(g_y + (size_t)src * 512 + c * 4);
    float* p = g_agg1 + (size_t)dst * 256 + c * 4;
    asm volatile("red.global.add.v4.f32 [%0], {%1,%2,%3,%4};"
                 :: "l"(p), "f"(v.x), "f"(v.y), "f"(v.z), "f"(v.w) : "memory");
    if (c == 0) atomicAdd(g_cnt + dst, 1.0f);
}

// ---------------------------------------------------------------------------
// h = relu(agg1/max(cnt,1) + y_r + b1)
// ---------------------------------------------------------------------------
__global__ void hidden_kernel(const float* __restrict__ b1) {
    int t = blockIdx.x * 256 + threadIdx.x;
    if (t >= N_NODES * 64) return;
    int i = t >> 6, c = t & 63;
    float inv = 1.0f / fmaxf(g_cnt[i], 1.0f);
    float4 a  = *reinterpret_cast<const float4*>(g_agg1 + (size_t)i * 256 + c * 4);
    float4 yr = *reinterpret_cast<const float4*>(g_y + (size_t)i * 512 + 256 + c * 4);
    float4 bb = *reinterpret_cast<const float4*>(b1 + c * 4);
    float4 o;
    o.x = fmaxf(fmaf(a.x, inv, yr.x + bb.x), 0.f);
    o.y = fmaxf(fmaf(a.y, inv, yr.y + bb.y), 0.f);
    o.z = fmaxf(fmaf(a.z, inv, yr.z + bb.z), 0.f);
    o.w = fmaxf(fmaf(a.w, inv, yr.w + bb.w), 0.f);
    *reinterpret_cast<float4*>(g_h + (size_t)i * 256 + c * 4) = o;
}

// ---------------------------------------------------------------------------
// layer-2 projection: z[i] = { h[i]@W2_l^T (2), h[i]@W2_r^T (2) }
// one warp per node, 8 warps per block, W2 staged in smem
// ---------------------------------------------------------------------------
__global__ void __launch_bounds__(256) layer2_kernel(
    const float* __restrict__ W2l, const float* __restrict__ W2r)
{
    __shared__ float w[4][256];
    int tid = threadIdx.x;
    float* ws = &w[0][0];
#pragma unroll
    for (int j = 0; j < 4; j++) {
        int idx = tid + j * 256;
        ws[idx] = (idx < 512) ? W2l[idx] : W2r[idx - 512];
    }
    __syncthreads();

    int warp = tid >> 5, lane = tid & 31;
    int node = blockIdx.x * 8 + warp;
    if (node >= N_NODES) return;

    float a0 = 0.f, a1 = 0.f, a2 = 0.f, a3 = 0.f;
    const float* hp = g_h + (size_t)node * 256;
#pragma unroll
    for (int j = 0; j < 8; j++) {
        int c = j * 32 + lane;
        float hv = hp[c];
        a0 = fmaf(hv, w[0][c], a0);
        a1 = fmaf(hv, w[1][c], a1);
        a2 = fmaf(hv, w[2][c], a2);
        a3 = fmaf(hv, w[3][c], a3);
    }
#pragma unroll
    for (int s = 16; s > 0; s >>= 1) {
        a0 += __shfl_xor_sync(0xFFFFFFFFu, a0, s);
        a1 += __shfl_xor_sync(0xFFFFFFFFu, a1, s);
        a2 += __shfl_xor_sync(0xFFFFFFFFu, a2, s);
        a3 += __shfl_xor_sync(0xFFFFFFFFu, a3, s);
    }
    if (lane == 0) {
        float4* zp = reinterpret_cast<float4*>(g_z + (size_t)node * 4);
        *zp = make_float4(a0, a1, a2, a3);
    }
}

// ---------------------------------------------------------------------------
// edge scatter of z_l (2 floats/edge)
// ---------------------------------------------------------------------------
__global__ void scatter2_kernel(const int* __restrict__ ei) {
    int e = blockIdx.x * 256 + threadIdx.x;
    if (e >= N_EDGES) return;
    int src = ei[e];
    int dst = ei[N_EDGES + e];
    float z0 = g_z[(size_t)src * 4 + 0];
    float z1 = g_z[(size_t)src * 4 + 1];
    atomicAdd(g_agg2 + (size_t)dst * 2 + 0, z0);
    atomicAdd(g_agg2 + (size_t)dst * 2 + 1, z1);
}

// ---------------------------------------------------------------------------
// out = agg2/max(cnt,1) + z_r + b2
// ---------------------------------------------------------------------------
__global__ void final_kernel(const float* __restrict__ b2, float* __restrict__ out) {
    int i = blockIdx.x * 256 + threadIdx.x;
    if (i >= N_NODES) return;
    float inv = 1.0f / fmaxf(g_cnt[i], 1.0f);
    out[(size_t)i * 2 + 0] = fmaf(g_agg2[(size_t)i * 2 + 0], inv, g_z[(size_t)i * 4 + 2] + b2[0]);
    out[(size_t)i * 2 + 1] = fmaf(g_agg2[(size_t)i * 2 + 1], inv, g_z[(size_t)i * 4 + 3] + b2[1]);
}

extern "C" void kernel_launch(void* const* d_in, const int* in_sizes, int n_in,
                              void* d_out, int out_size) {
    const float* x    = (const float*)d_in[0];
    const int*   ei   = (const int*)d_in[1];
    const float* W1l  = (const float*)d_in[2];
    const float* b1   = (const float*)d_in[3];
    const float* W1r  = (const float*)d_in[4];
    const float* W2l  = (const float*)d_in[5];
    const float* b2   = (const float*)d_in[6];
    const float* W2r  = (const float*)d_in[7];
    float*       out  = (float*)d_out;

    const int M = N_NODES;

    // zero accumulators (covers agg1 float4 count = N*64, cnt, agg2)
    zero_kernel<<<(N_NODES * 64 + 255) / 256, 256>>>();

    dim3 g1((M + 127) / 128, 4);
    gemm1_kernel<<<g1, 256>>>(x, W1l, W1r, M);

    scatter1_kernel<<<(N_EDGES * 64 + 255) / 256, 256>>>(ei);

    hidden_kernel<<<(N_NODES * 64 + 255) / 256, 256>>>(b1);

    layer2_kernel<<<(N_NODES + 7) / 8, 256>>>(W2l, W2r);

    scatter2_kernel<<<(N_EDGES + 255) / 256, 256>>>(ei);

    final_kernel<<<(N_NODES + 255) / 256, 256>>>(b2, out);
}

// round 4
// speedup vs baseline: 2.1782x; 2.1782x over previous
#include <cuda_runtime.h>
#include <cuda_fp16.h>
#include <cstdint>

#define N_NODES 50000
#define N_EDGES 250000
#define D_IN    768
#define D_HID   256

#define M_PAD   50048           // 391 * 128
#define KA      1536            // [x_hi | x_lo]
#define KB      2304            // [W_hi | W_hi | W_lo]
#define KSTEPS  36              // 2304 / 64

__device__ float g_y[(size_t)N_NODES * 512];
__device__ float g_agg1[(size_t)N_NODES * 256];
__device__ float g_h[(size_t)N_NODES * 256];
__device__ float g_cnt[N_NODES];
__device__ float g_z[(size_t)N_NODES * 4];
__device__ float g_agg2[(size_t)N_NODES * 2];
__device__ __half g_A[(size_t)M_PAD * KA];   // padded rows stay 0
__device__ __half g_B[(size_t)512 * KB];

// ---------------------------------------------------------------------------
// helpers
// ---------------------------------------------------------------------------
__device__ __forceinline__ uint32_t smem_u32(const void* p) {
    uint32_t a;
    asm("{ .reg .u64 t; cvta.to.shared.u64 t, %1; cvt.u32.u64 %0, t; }" : "=r"(a) : "l"(p));
    return a;
}
__device__ __forceinline__ void cp16(uint32_t dst, const void* src) {
    asm volatile("cp.async.cg.shared.global [%0], [%1], 16;" :: "r"(dst), "l"(src));
}
__device__ __forceinline__ void cp_commit() { asm volatile("cp.async.commit_group;" ::: "memory"); }
template <int N> __device__ __forceinline__ void cp_wait() {
    asm volatile("cp.async.wait_group %0;" :: "n"(N) : "memory");
}
__device__ __forceinline__ void ldm_x4(uint32_t* r, uint32_t addr) {
    asm volatile("ldmatrix.sync.aligned.m8n8.x4.shared.b16 {%0,%1,%2,%3}, [%4];"
                 : "=r"(r[0]), "=r"(r[1]), "=r"(r[2]), "=r"(r[3]) : "r"(addr));
}
__device__ __forceinline__ void mma16816(float* d, const uint32_t* a, uint32_t b0, uint32_t b1) {
    asm volatile(
        "mma.sync.aligned.m16n8k16.row.col.f32.f16.f16.f32 "
        "{%0,%1,%2,%3}, {%4,%5,%6,%7}, {%8,%9}, {%0,%1,%2,%3};"
        : "+f"(d[0]), "+f"(d[1]), "+f"(d[2]), "+f"(d[3])
        : "r"(a[0]), "r"(a[1]), "r"(a[2]), "r"(a[3]), "r"(b0), "r"(b1));
}

// ---------------------------------------------------------------------------
// zero scratch accumulators
// ---------------------------------------------------------------------------
__global__ void zero_kernel() {
    int t = blockIdx.x * 256 + threadIdx.x;
    if (t < N_NODES * 64) reinterpret_cast<float4*>(g_agg1)[t] = make_float4(0.f, 0.f, 0.f, 0.f);
    if (t < N_NODES)      g_cnt[t] = 0.f;
    if (t < N_NODES * 2)  g_agg2[t] = 0.f;
}

// ---------------------------------------------------------------------------
// convert x -> split fp16 A' = [hi | lo], K=1536
// ---------------------------------------------------------------------------
__global__ void conv_x_kernel(const float* __restrict__ x) {
    int t = blockIdx.x * 256 + threadIdx.x;
    if (t >= N_NODES * (D_IN / 4)) return;
    int m = t / (D_IN / 4), c4 = t % (D_IN / 4);
    float4 v = *reinterpret_cast<const float4*>(x + (size_t)m * D_IN + c4 * 4);
    float vv[4] = {v.x, v.y, v.z, v.w};
    __half hi[4], lo[4];
#pragma unroll
    for (int i = 0; i < 4; i++) {
        hi[i] = __float2half_rn(vv[i]);
        lo[i] = __float2half_rn(vv[i] - __half2float(hi[i]));
    }
    __half* base = g_A + (size_t)m * KA + c4 * 4;
    *reinterpret_cast<uint2*>(base)       = *reinterpret_cast<uint2*>(hi);
    *reinterpret_cast<uint2*>(base + 768) = *reinterpret_cast<uint2*>(lo);
}

// ---------------------------------------------------------------------------
// convert W1_l/W1_r -> B' rows 0..255 / 256..511, K layout [hi | hi | lo]
// ---------------------------------------------------------------------------
__global__ void conv_w_kernel(const float* __restrict__ Wl, const float* __restrict__ Wr) {
    int t = blockIdx.x * 256 + threadIdx.x;
    if (t >= 512 * D_IN) return;
    int r = t / D_IN, c = t % D_IN;
    float v = (r < 256) ? Wl[(size_t)r * D_IN + c] : Wr[(size_t)(r - 256) * D_IN + c];
    __half hi = __float2half_rn(v);
    __half lo = __float2half_rn(v - __half2float(hi));
    __half* base = g_B + (size_t)r * KB;
    base[c] = hi; base[768 + c] = hi; base[1536 + c] = lo;
}

// ---------------------------------------------------------------------------
// tensor-core GEMM (mma.sync fp16): g_y[m, bx*128 + n] = A'[m,:] . B'[n,:]
// 128x128 tile, BK=64, 8 warps (4M x 2N), double-buffered cp.async
// smem rows padded to 144B for conflict-free ldmatrix
// ---------------------------------------------------------------------------
#define STAGE_BYTES 36864               // A (128*144) + B (128*144)
#define SMEM_BYTES  (2 * STAGE_BYTES)   // 73728

__global__ void __launch_bounds__(256, 2) gemm_tc_kernel() {
    extern __shared__ char smem[];
    const uint32_t sb  = smem_u32(smem);
    const int tid  = threadIdx.x;
    const int lane = tid & 31;
    const int wid  = tid >> 5;
    const int wm   = wid & 3;           // 0..3  (M)
    const int wn   = wid >> 2;          // 0..1  (N)
    const int nb    = blockIdx.x * 128; // n-slice (4)
    const int mbase = blockIdx.y * 128; // m-stripe (391)

    auto a_kb = [](int s) -> int {
        return (s < 12) ? s * 64 : ((s < 24) ? 768 + (s - 12) * 64 : (s - 24) * 64);
    };

    auto issue = [&](int s, int buf) {
        const int akb = a_kb(s);
        const int bkb = s * 64;
        const uint32_t abase = sb + buf * STAGE_BYTES;
        const uint32_t bbase = abase + 18432;
#pragma unroll
        for (int j = 0; j < 4; j++) {
            int id  = tid + j * 256;
            int row = id >> 3, c = id & 7;
            cp16(abase + row * 144 + c * 16, g_A + (size_t)(mbase + row) * KA + akb + c * 8);
            cp16(bbase + row * 144 + c * 16, g_B + (size_t)(nb  + row) * KB + bkb + c * 8);
        }
        cp_commit();
    };

    float d[2][8][4];
#pragma unroll
    for (int mt = 0; mt < 2; mt++)
#pragma unroll
        for (int nt = 0; nt < 8; nt++)
#pragma unroll
            for (int q = 0; q < 4; q++) d[mt][nt][q] = 0.f;

    issue(0, 0);

    for (int s = 0; s < KSTEPS; s++) {
        const int buf = s & 1;
        if (s + 1 < KSTEPS) { issue(s + 1, buf ^ 1); cp_wait<1>(); }
        else                { cp_wait<0>(); }
        __syncthreads();

        const uint32_t abase = sb + buf * STAGE_BYTES + (wm * 32) * 144;
        const uint32_t bbase = sb + buf * STAGE_BYTES + 18432 + (wn * 64) * 144;
        const int arow = lane & 15, ahalf = lane >> 4;
        const int brow = (lane & 7) + ((lane >> 4) & 1) * 8, bhalf = (lane >> 3) & 1;

#pragma unroll
        for (int kk = 0; kk < 4; kk++) {
            uint32_t ar[2][4];
#pragma unroll
            for (int mt = 0; mt < 2; mt++)
                ldm_x4(ar[mt], abase + (mt * 16 + arow) * 144 + kk * 32 + ahalf * 16);
            uint32_t br[4][4];
#pragma unroll
            for (int bt = 0; bt < 4; bt++)
                ldm_x4(br[bt], bbase + (bt * 16 + brow) * 144 + kk * 32 + bhalf * 16);
#pragma unroll
            for (int mt = 0; mt < 2; mt++)
#pragma unroll
                for (int nt = 0; nt < 8; nt++)
                    mma16816(d[mt][nt], ar[mt], br[nt >> 1][(nt & 1) * 2],
                             br[nt >> 1][(nt & 1) * 2 + 1]);
        }
        __syncthreads();
    }

    // epilogue: fragment layout c0,c1 -> (row, col..col+1); c2,c3 -> (row+8, ...)
#pragma unroll
    for (int mt = 0; mt < 2; mt++) {
        int row = mbase + wm * 32 + mt * 16 + (lane >> 2);
#pragma unroll
        for (int nt = 0; nt < 8; nt++) {
            int col = nb + wn * 64 + nt * 8 + (lane & 3) * 2;
            if (row < N_NODES)
                *reinterpret_cast<float2*>(g_y + (size_t)row * 512 + col) =
                    make_float2(d[mt][nt][0], d[mt][nt][1]);
            if (row + 8 < N_NODES)
                *reinterpret_cast<float2*>(g_y + (size_t)(row + 8) * 512 + col) =
                    make_float2(d[mt][nt][2], d[mt][nt][3]);
        }
    }
}

// ---------------------------------------------------------------------------
// edge scatter of y_l with vectorized global reductions (+degree count)
// ---------------------------------------------------------------------------
__global__ void scatter1_kernel(const int* __restrict__ ei) {
    int t = blockIdx.x * 256 + threadIdx.x;
    int e = t >> 6;
    int c = t & 63;
    if (e >= N_EDGES) return;
    int src = ei[e];
    int dst = ei[N_EDGES + e];
    float4 v = *reinterpret_cast<const float4*>(g_y + (size_t)src * 512 + c * 4);
    float* p = g_agg1 + (size_t)dst * 256 + c * 4;
    asm volatile("red.global.add.v4.f32 [%0], {%1,%2,%3,%4};"
                 :: "l"(p), "f"(v.x), "f"(v.y), "f"(v.z), "f"(v.w) : "memory");
    if (c == 0) atomicAdd(g_cnt + dst, 1.0f);
}

// ---------------------------------------------------------------------------
// h = relu(agg1/max(cnt,1) + y_r + b1)
// ---------------------------------------------------------------------------
__global__ void hidden_kernel(const float* __restrict__ b1) {
    int t = blockIdx.x * 256 + threadIdx.x;
    if (t >= N_NODES * 64) return;
    int i = t >> 6, c = t & 63;
    float inv = 1.0f / fmaxf(g_cnt[i], 1.0f);
    float4 a  = *reinterpret_cast<const float4*>(g_agg1 + (size_t)i * 256 + c * 4);
    float4 yr = *reinterpret_cast<const float4*>(g_y + (size_t)i * 512 + 256 + c * 4);
    float4 bb = *reinterpret_cast<const float4*>(b1 + c * 4);
    float4 o;
    o.x = fmaxf(fmaf(a.x, inv, yr.x + bb.x), 0.f);
    o.y = fmaxf(fmaf(a.y, inv, yr.y + bb.y), 0.f);
    o.z = fmaxf(fmaf(a.z, inv, yr.z + bb.z), 0.f);
    o.w = fmaxf(fmaf(a.w, inv, yr.w + bb.w), 0.f);
    *reinterpret_cast<float4*>(g_h + (size_t)i * 256 + c * 4) = o;
}

// ---------------------------------------------------------------------------
// layer-2 projection per node (warp per node)
// ---------------------------------------------------------------------------
__global__ void __launch_bounds__(256) layer2_kernel(
    const float* __restrict__ W2l, const float* __restrict__ W2r)
{
    __shared__ float w[4][256];
    int tid = threadIdx.x;
    float* ws = &w[0][0];
#pragma unroll
    for (int j = 0; j < 4; j++) {
        int idx = tid + j * 256;
        ws[idx] = (idx < 512) ? W2l[idx] : W2r[idx - 512];
    }
    __syncthreads();
    int warp = tid >> 5, lane = tid & 31;
    int node = blockIdx.x * 8 + warp;
    if (node >= N_NODES) return;
    float a0 = 0.f, a1 = 0.f, a2 = 0.f, a3 = 0.f;
    const float* hp = g_h + (size_t)node * 256;
#pragma unroll
    for (int j = 0; j < 8; j++) {
        int c = j * 32 + lane;
        float hv = hp[c];
        a0 = fmaf(hv, w[0][c], a0);
        a1 = fmaf(hv, w[1][c], a1);
        a2 = fmaf(hv, w[2][c], a2);
        a3 = fmaf(hv, w[3][c], a3);
    }
#pragma unroll
    for (int s = 16; s > 0; s >>= 1) {
        a0 += __shfl_xor_sync(0xFFFFFFFFu, a0, s);
        a1 += __shfl_xor_sync(0xFFFFFFFFu, a1, s);
        a2 += __shfl_xor_sync(0xFFFFFFFFu, a2, s);
        a3 += __shfl_xor_sync(0xFFFFFFFFu, a3, s);
    }
    if (lane == 0)
        *reinterpret_cast<float4*>(g_z + (size_t)node * 4) = make_float4(a0, a1, a2, a3);
}

__global__ void scatter2_kernel(const int* __restrict__ ei) {
    int e = blockIdx.x * 256 + threadIdx.x;
    if (e >= N_EDGES) return;
    int src = ei[e];
    int dst = ei[N_EDGES + e];
    atomicAdd(g_agg2 + (size_t)dst * 2 + 0, g_z[(size_t)src * 4 + 0]);
    atomicAdd(g_agg2 + (size_t)dst * 2 + 1, g_z[(size_t)src * 4 + 1]);
}

__global__ void final_kernel(const float* __restrict__ b2, float* __restrict__ out) {
    int i = blockIdx.x * 256 + threadIdx.x;
    if (i >= N_NODES) return;
    float inv = 1.0f / fmaxf(g_cnt[i], 1.0f);
    out[(size_t)i * 2 + 0] = fmaf(g_agg2[(size_t)i * 2 + 0], inv, g_z[(size_t)i * 4 + 2] + b2[0]);
    out[(size_t)i * 2 + 1] = fmaf(g_agg2[(size_t)i * 2 + 1], inv, g_z[(size_t)i * 4 + 3] + b2[1]);
}

extern "C" void kernel_launch(void* const* d_in, const int* in_sizes, int n_in,
                              void* d_out, int out_size) {
    const float* x    = (const float*)d_in[0];
    const int*   ei   = (const int*)d_in[1];
    const float* W1l  = (const float*)d_in[2];
    const float* b1   = (const float*)d_in[3];
    const float* W1r  = (const float*)d_in[4];
    const float* W2l  = (const float*)d_in[5];
    const float* b2   = (const float*)d_in[6];
    const float* W2r  = (const float*)d_in[7];
    float*       out  = (float*)d_out;

    static bool attr_set = false;
    if (!attr_set) {
        cudaFuncSetAttribute(gemm_tc_kernel,
                             cudaFuncAttributeMaxDynamicSharedMemorySize, SMEM_BYTES);
        attr_set = true;
    }

    zero_kernel<<<(N_NODES * 64 + 255) / 256, 256>>>();
    conv_x_kernel<<<(N_NODES * (D_IN / 4) + 255) / 256, 256>>>(x);
    conv_w_kernel<<<(512 * D_IN + 255) / 256, 256>>>(W1l, W1r);

    dim3 gg(4, M_PAD / 128);
    gemm_tc_kernel<<<gg, 256, SMEM_BYTES>>>();

    scatter1_kernel<<<(N_EDGES * 64 + 255) / 256, 256>>>(ei);
    hidden_kernel<<<(N_NODES * 64 + 255) / 256, 256>>>(b1);
    layer2_kernel<<<(N_NODES + 7) / 8, 256>>>(W2l, W2r);
    scatter2_kernel<<<(N_EDGES + 255) / 256, 256>>>(ei);
    final_kernel<<<(N_NODES + 255) / 256, 256>>>(b2, out);
}

// round 6
// speedup vs baseline: 2.8026x; 1.2867x over previous
#include <cuda_runtime.h>
#include <cuda_fp16.h>
#include <cstdint>

#define N_NODES 50000
#define N_EDGES 250000
#define D_IN    768
#define D_HID   256

#define M_PAD   50048           // 391 * 128
#define KA      1536            // [x_hi | x_lo]
#define KSTEPS  24              // 1536 / 64

__device__ float g_y[(size_t)N_NODES * 512];
__device__ float g_agg1[(size_t)N_NODES * 256];
__device__ float g_h[(size_t)N_NODES * 256];
__device__ float g_cnt[N_NODES];
__device__ float g_z[(size_t)N_NODES * 4];
__device__ float g_agg2[(size_t)N_NODES * 2];
__device__ __half g_A[(size_t)M_PAD * KA];   // padded rows stay 0
__device__ __half g_B[(size_t)512 * D_IN];   // W_hi only (rows 0..255 = W1_l, 256..511 = W1_r)

// ---------------------------------------------------------------------------
// helpers
// ---------------------------------------------------------------------------
__device__ __forceinline__ uint32_t smem_u32(const void* p) {
    uint32_t a;
    asm("{ .reg .u64 t; cvta.to.shared.u64 t, %1; cvt.u32.u64 %0, t; }" : "=r"(a) : "l"(p));
    return a;
}
__device__ __forceinline__ void cp16(uint32_t dst, const void* src) {
    asm volatile("cp.async.cg.shared.global [%0], [%1], 16;" :: "r"(dst), "l"(src));
}
__device__ __forceinline__ void cp_commit() { asm volatile("cp.async.commit_group;" ::: "memory"); }
template <int N> __device__ __forceinline__ void cp_wait() {
    asm volatile("cp.async.wait_group %0;" :: "n"(N) : "memory");
}
__device__ __forceinline__ void ldm_x4(uint32_t* r, uint32_t addr) {
    asm volatile("ldmatrix.sync.aligned.m8n8.x4.shared.b16 {%0,%1,%2,%3}, [%4];"
                 : "=r"(r[0]), "=r"(r[1]), "=r"(r[2]), "=r"(r[3]) : "r"(addr));
}
__device__ __forceinline__ void mma16816(float* d, const uint32_t* a, uint32_t b0, uint32_t b1) {
    asm volatile(
        "mma.sync.aligned.m16n8k16.row.col.f32.f16.f16.f32 "
        "{%0,%1,%2,%3}, {%4,%5,%6,%7}, {%8,%9}, {%0,%1,%2,%3};"
        : "+f"(d[0]), "+f"(d[1]), "+f"(d[2]), "+f"(d[3])
        : "r"(a[0]), "r"(a[1]), "r"(a[2]), "r"(a[3]), "r"(b0), "r"(b1));
}

// ---------------------------------------------------------------------------
// convert x -> split fp16 A' = [hi | lo]; also zero the scratch accumulators.
// GRID MUST COVER N_NODES*(D_IN/4) = N_NODES*192 threads.
// ---------------------------------------------------------------------------
__global__ void conv_x_kernel(const float* __restrict__ x) {
    int t = blockIdx.x * 256 + threadIdx.x;
    // zeroing duties (each guarded independently)
    if (t < N_NODES * 64) reinterpret_cast<float4*>(g_agg1)[t] = make_float4(0.f, 0.f, 0.f, 0.f);
    if (t < N_NODES)      g_cnt[t] = 0.f;
    if (t < N_NODES * 2)  g_agg2[t] = 0.f;

    if (t >= N_NODES * (D_IN / 4)) return;
    int m = t / (D_IN / 4), c4 = t % (D_IN / 4);
    float4 v = *reinterpret_cast<const float4*>(x + (size_t)m * D_IN + c4 * 4);
    float vv[4] = {v.x, v.y, v.z, v.w};
    __half hi[4], lo[4];
#pragma unroll
    for (int i = 0; i < 4; i++) {
        hi[i] = __float2half_rn(vv[i]);
        lo[i] = __float2half_rn(vv[i] - __half2float(hi[i]));
    }
    __half* base = g_A + (size_t)m * KA + c4 * 4;
    *reinterpret_cast<uint2*>(base)       = *reinterpret_cast<uint2*>(hi);
    *reinterpret_cast<uint2*>(base + 768) = *reinterpret_cast<uint2*>(lo);
}

// ---------------------------------------------------------------------------
// convert W1_l/W1_r -> fp16 B rows 0..255 / 256..511
// ---------------------------------------------------------------------------
__global__ void conv_w_kernel(const float* __restrict__ Wl, const float* __restrict__ Wr) {
    int t = blockIdx.x * 256 + threadIdx.x;
    if (t >= 512 * D_IN) return;
    int r = t / D_IN, c = t % D_IN;
    float v = (r < 256) ? Wl[(size_t)r * D_IN + c] : Wr[(size_t)(r - 256) * D_IN + c];
    g_B[(size_t)r * D_IN + c] = __float2half_rn(v);
}

// ---------------------------------------------------------------------------
// tensor-core GEMM (mma.sync fp16): g_y[m, bx*128+n] = sum_k A'[m,k]*Wh[n, k%768]
// 128x128 tile, BK=64, 8 warps (4M x 2N), 3-stage cp.async, 1 sync/iter
// smem rows padded to 144B for conflict-free ldmatrix
// ---------------------------------------------------------------------------
#define STAGE_BYTES 36864               // A (128*144) + B (128*144)
#define SMEM_BYTES  (3 * STAGE_BYTES)   // 110592

__global__ void __launch_bounds__(256, 2) gemm_tc_kernel() {
    extern __shared__ char smem[];
    const uint32_t sb  = smem_u32(smem);
    const int tid  = threadIdx.x;
    const int lane = tid & 31;
    const int wid  = tid >> 5;
    const int wm   = wid & 3;           // 0..3  (M)
    const int wn   = wid >> 2;          // 0..1  (N)
    const int nb    = blockIdx.x * 128; // n-slice (4)
    const int mbase = blockIdx.y * 128; // m-stripe (391)

    auto issue = [&](int s, int buf) {
        const int akb = (s < 12) ? s * 64 : 768 + (s - 12) * 64;
        const int bkb = (s % 12) * 64;
        const uint32_t abase = sb + buf * STAGE_BYTES;
        const uint32_t bbase = abase + 18432;
#pragma unroll
        for (int j = 0; j < 4; j++) {
            int id  = tid + j * 256;
            int row = id >> 3, c = id & 7;
            cp16(abase + row * 144 + c * 16, g_A + (size_t)(mbase + row) * KA + akb + c * 8);
            cp16(bbase + row * 144 + c * 16, g_B + (size_t)(nb  + row) * D_IN + bkb + c * 8);
        }
        cp_commit();
    };

    float d[2][8][4];
#pragma unroll
    for (int mt = 0; mt < 2; mt++)
#pragma unroll
        for (int nt = 0; nt < 8; nt++)
#pragma unroll
            for (int q = 0; q < 4; q++) d[mt][nt][q] = 0.f;

    issue(0, 0);
    issue(1, 1);

    const int arow = lane & 15, ahalf = lane >> 4;
    const int brow = (lane & 7) + ((lane >> 4) & 1) * 8, bhalf = (lane >> 3) & 1;

    for (int s = 0; s < KSTEPS; s++) {
        if (s == KSTEPS - 1) cp_wait<0>(); else cp_wait<1>();
        __syncthreads();
        if (s + 2 < KSTEPS) issue(s + 2, (s + 2) % 3);

        const int buf = s % 3;
        const uint32_t abase = sb + buf * STAGE_BYTES + (wm * 32) * 144;
        const uint32_t bbase = sb + buf * STAGE_BYTES + 18432 + (wn * 64) * 144;

#pragma unroll
        for (int kk = 0; kk < 4; kk++) {
            uint32_t ar[2][4];
#pragma unroll
            for (int mt = 0; mt < 2; mt++)
                ldm_x4(ar[mt], abase + (mt * 16 + arow) * 144 + kk * 32 + ahalf * 16);
            uint32_t br[4][4];
#pragma unroll
            for (int bt = 0; bt < 4; bt++)
                ldm_x4(br[bt], bbase + (bt * 16 + brow) * 144 + kk * 32 + bhalf * 16);
#pragma unroll
            for (int mt = 0; mt < 2; mt++)
#pragma unroll
                for (int nt = 0; nt < 8; nt++)
                    mma16816(d[mt][nt], ar[mt], br[nt >> 1][(nt & 1) * 2],
                             br[nt >> 1][(nt & 1) * 2 + 1]);
        }
    }

    // epilogue
#pragma unroll
    for (int mt = 0; mt < 2; mt++) {
        int row = mbase + wm * 32 + mt * 16 + (lane >> 2);
#pragma unroll
        for (int nt = 0; nt < 8; nt++) {
            int col = nb + wn * 64 + nt * 8 + (lane & 3) * 2;
            if (row < N_NODES)
                *reinterpret_cast<float2*>(g_y + (size_t)row * 512 + col) =
                    make_float2(d[mt][nt][0], d[mt][nt][1]);
            if (row + 8 < N_NODES)
                *reinterpret_cast<float2*>(g_y + (size_t)(row + 8) * 512 + col) =
                    make_float2(d[mt][nt][2], d[mt][nt][3]);
        }
    }
}

// ---------------------------------------------------------------------------
// edge scatter of y_l with vectorized global reductions (+degree count)
// ---------------------------------------------------------------------------
__global__ void scatter1_kernel(const int* __restrict__ ei) {
    int t = blockIdx.x * 256 + threadIdx.x;
    int e = t >> 6;
    int c = t & 63;
    if (e >= N_EDGES) return;
    int src = ei[e];
    int dst = ei[N_EDGES + e];
    float4 v = *reinterpret_cast<const float4*>(g_y + (size_t)src * 512 + c * 4);
    float* p = g_agg1 + (size_t)dst * 256 + c * 4;
    asm volatile("red.global.add.v4.f32 [%0], {%1,%2,%3,%4};"
                 :: "l"(p), "f"(v.x), "f"(v.y), "f"(v.z), "f"(v.w) : "memory");
    if (c == 0) atomicAdd(g_cnt + dst, 1.0f);
}

// ---------------------------------------------------------------------------
// h = relu(agg1/max(cnt,1) + y_r + b1)
// ---------------------------------------------------------------------------
__global__ void hidden_kernel(const float* __restrict__ b1) {
    int t = blockIdx.x * 256 + threadIdx.x;
    if (t >= N_NODES * 64) return;
    int i = t >> 6, c = t & 63;
    float inv = 1.0f / fmaxf(g_cnt[i], 1.0f);
    float4 a  = *reinterpret_cast<const float4*>(g_agg1 + (size_t)i * 256 + c * 4);
    float4 yr = *reinterpret_cast<const float4*>(g_y + (size_t)i * 512 + 256 + c * 4);
    float4 bb = *reinterpret_cast<const float4*>(b1 + c * 4);
    float4 o;
    o.x = fmaxf(fmaf(a.x, inv, yr.x + bb.x), 0.f);
    o.y = fmaxf(fmaf(a.y, inv, yr.y + bb.y), 0.f);
    o.z = fmaxf(fmaf(a.z, inv, yr.z + bb.z), 0.f);
    o.w = fmaxf(fmaf(a.w, inv, yr.w + bb.w), 0.f);
    *reinterpret_cast<float4*>(g_h + (size_t)i * 256 + c * 4) = o;
}

// ---------------------------------------------------------------------------
// layer-2 projection per node (warp per node)
// ---------------------------------------------------------------------------
__global__ void __launch_bounds__(256) layer2_kernel(
    const float* __restrict__ W2l, const float* __restrict__ W2r)
{
    __shared__ float w[4][256];
    int tid = threadIdx.x;
    float* ws = &w[0][0];
#pragma unroll
    for (int j = 0; j < 4; j++) {
        int idx = tid + j * 256;
        ws[idx] = (idx < 512) ? W2l[idx] : W2r[idx - 512];
    }
    __syncthreads();
    int warp = tid >> 5, lane = tid & 31;
    int node = blockIdx.x * 8 + warp;
    if (node >= N_NODES) return;
    float a0 = 0.f, a1 = 0.f, a2 = 0.f, a3 = 0.f;
    const float* hp = g_h + (size_t)node * 256;
#pragma unroll
    for (int j = 0; j < 8; j++) {
        int c = j * 32 + lane;
        float hv = hp[c];
        a0 = fmaf(hv, w[0][c], a0);
        a1 = fmaf(hv, w[1][c], a1);
        a2 = fmaf(hv, w[2][c], a2);
        a3 = fmaf(hv, w[3][c], a3);
    }
#pragma unroll
    for (int s = 16; s > 0; s >>= 1) {
        a0 += __shfl_xor_sync(0xFFFFFFFFu, a0, s);
        a1 += __shfl_xor_sync(0xFFFFFFFFu, a1, s);
        a2 += __shfl_xor_sync(0xFFFFFFFFu, a2, s);
        a3 += __shfl_xor_sync(0xFFFFFFFFu, a3, s);
    }
    if (lane == 0)
        *reinterpret_cast<float4*>(g_z + (size_t)node * 4) = make_float4(a0, a1, a2, a3);
}

__global__ void scatter2_kernel(const int* __restrict__ ei) {
    int e = blockIdx.x * 256 + threadIdx.x;
    if (e >= N_EDGES) return;
    int src = ei[e];
    int dst = ei[N_EDGES + e];
    atomicAdd(g_agg2 + (size_t)dst * 2 + 0, g_z[(size_t)src * 4 + 0]);
    atomicAdd(g_agg2 + (size_t)dst * 2 + 1, g_z[(size_t)src * 4 + 1]);
}

__global__ void final_kernel(const float* __restrict__ b2, float* __restrict__ out) {
    int i = blockIdx.x * 256 + threadIdx.x;
    if (i >= N_NODES) return;
    float inv = 1.0f / fmaxf(g_cnt[i], 1.0f);
    out[(size_t)i * 2 + 0] = fmaf(g_agg2[(size_t)i * 2 + 0], inv, g_z[(size_t)i * 4 + 2] + b2[0]);
    out[(size_t)i * 2 + 1] = fmaf(g_agg2[(size_t)i * 2 + 1], inv, g_z[(size_t)i * 4 + 3] + b2[1]);
}

extern "C" void kernel_launch(void* const* d_in, const int* in_sizes, int n_in,
                              void* d_out, int out_size) {
    const float* x    = (const float*)d_in[0];
    const int*   ei   = (const int*)d_in[1];
    const float* W1l  = (const float*)d_in[2];
    const float* b1   = (const float*)d_in[3];
    const float* W1r  = (const float*)d_in[4];
    const float* W2l  = (const float*)d_in[5];
    const float* b2   = (const float*)d_in[6];
    const float* W2r  = (const float*)d_in[7];
    float*       out  = (float*)d_out;

    static bool attr_set = false;
    if (!attr_set) {
        cudaFuncSetAttribute(gemm_tc_kernel,
                             cudaFuncAttributeMaxDynamicSharedMemorySize, SMEM_BYTES);
        attr_set = true;
    }

    // grid covers conversion work: N_NODES * 192 threads (zeroing guards are inside)
    conv_x_kernel<<<(N_NODES * (D_IN / 4) + 255) / 256, 256>>>(x);
    conv_w_kernel<<<(512 * D_IN + 255) / 256, 256>>>(W1l, W1r);

    dim3 gg(4, M_PAD / 128);
    gemm_tc_kernel<<<gg, 256, SMEM_BYTES>>>();

    scatter1_kernel<<<(N_EDGES * 64 + 255) / 256, 256>>>(ei);
    hidden_kernel<<<(N_NODES * 64 + 255) / 256, 256>>>(b1);
    layer2_kernel<<<(N_NODES + 7) / 8, 256>>>(W2l, W2r);
    scatter2_kernel<<<(N_EDGES + 255) / 256, 256>>>(ei);
    final_kernel<<<(N_NODES + 255) / 256, 256>>>(b2, out);
}

// round 7
// speedup vs baseline: 3.9682x; 1.4159x over previous
#include <cuda_runtime.h>
#include <cuda_fp16.h>
#include <cstdint>

#define N_NODES 50000
#define N_EDGES 250000
#define D_IN    768
#define D_HID   256

#define M_PAD   50048           // 391 * 128
#define KSTEPS  12              // 768 / 64

__device__ __half g_yl[(size_t)N_NODES * 256];  // y_l = x@W1_l^T  (fp16)
__device__ float  g_yr[(size_t)N_NODES * 256];  // y_r = x@W1_r^T  (fp32)
__device__ float  g_agg1[(size_t)N_NODES * 256];
__device__ float  g_h[(size_t)N_NODES * 256];
__device__ float  g_cnt[N_NODES];
__device__ float  g_z[(size_t)N_NODES * 4];
__device__ float  g_agg2[(size_t)N_NODES * 2];
__device__ __half g_A[(size_t)M_PAD * D_IN];    // x in fp16; padded rows stay 0
__device__ __half g_B[(size_t)512 * D_IN];      // rows 0..255 = W1_l, 256..511 = W1_r

// ---------------------------------------------------------------------------
// helpers
// ---------------------------------------------------------------------------
__device__ __forceinline__ uint32_t smem_u32(const void* p) {
    uint32_t a;
    asm("{ .reg .u64 t; cvta.to.shared.u64 t, %1; cvt.u32.u64 %0, t; }" : "=r"(a) : "l"(p));
    return a;
}
__device__ __forceinline__ void cp16(uint32_t dst, const void* src) {
    asm volatile("cp.async.cg.shared.global [%0], [%1], 16;" :: "r"(dst), "l"(src));
}
__device__ __forceinline__ void cp_commit() { asm volatile("cp.async.commit_group;" ::: "memory"); }
template <int N> __device__ __forceinline__ void cp_wait() {
    asm volatile("cp.async.wait_group %0;" :: "n"(N) : "memory");
}
__device__ __forceinline__ void ldm_x4(uint32_t* r, uint32_t addr) {
    asm volatile("ldmatrix.sync.aligned.m8n8.x4.shared.b16 {%0,%1,%2,%3}, [%4];"
                 : "=r"(r[0]), "=r"(r[1]), "=r"(r[2]), "=r"(r[3]) : "r"(addr));
}
__device__ __forceinline__ void mma16816(float* d, const uint32_t* a, uint32_t b0, uint32_t b1) {
    asm volatile(
        "mma.sync.aligned.m16n8k16.row.col.f32.f16.f16.f32 "
        "{%0,%1,%2,%3}, {%4,%5,%6,%7}, {%8,%9}, {%0,%1,%2,%3};"
        : "+f"(d[0]), "+f"(d[1]), "+f"(d[2]), "+f"(d[3])
        : "r"(a[0]), "r"(a[1]), "r"(a[2]), "r"(a[3]), "r"(b0), "r"(b1));
}

// ---------------------------------------------------------------------------
// convert x -> fp16; also zero the scratch accumulators.
// grid covers N_NODES*(D_IN/4) = N_NODES*192 threads.
// ---------------------------------------------------------------------------
__global__ void conv_x_kernel(const float* __restrict__ x) {
    int t = blockIdx.x * 256 + threadIdx.x;
    if (t < N_NODES * 64) reinterpret_cast<float4*>(g_agg1)[t] = make_float4(0.f, 0.f, 0.f, 0.f);
    if (t < N_NODES)      g_cnt[t] = 0.f;
    if (t < N_NODES * 2)  g_agg2[t] = 0.f;

    if (t >= N_NODES * (D_IN / 4)) return;
    int m = t / (D_IN / 4), c4 = t % (D_IN / 4);
    float4 v = *reinterpret_cast<const float4*>(x + (size_t)m * D_IN + c4 * 4);
    __half2 h0 = __floats2half2_rn(v.x, v.y);
    __half2 h1 = __floats2half2_rn(v.z, v.w);
    *reinterpret_cast<uint2*>(g_A + (size_t)m * D_IN + c4 * 4) =
        make_uint2(*reinterpret_cast<uint32_t*>(&h0), *reinterpret_cast<uint32_t*>(&h1));
}

// ---------------------------------------------------------------------------
// convert W1_l/W1_r -> fp16 B rows 0..255 / 256..511
// ---------------------------------------------------------------------------
__global__ void conv_w_kernel(const float* __restrict__ Wl, const float* __restrict__ Wr) {
    int t = blockIdx.x * 256 + threadIdx.x;
    if (t >= 512 * D_IN) return;
    int r = t / D_IN, c = t % D_IN;
    float v = (r < 256) ? Wl[(size_t)r * D_IN + c] : Wr[(size_t)(r - 256) * D_IN + c];
    g_B[(size_t)r * D_IN + c] = __float2half_rn(v);
}

// ---------------------------------------------------------------------------
// tensor-core GEMM (mma.sync fp16), K=768
// 128x128 tile, BK=64, 8 warps (4M x 2N), 3-stage cp.async, 1 sync/iter
// blockIdx.x: 0,1 -> y_l (fp16 out), 2,3 -> y_r (fp32 out)
// ---------------------------------------------------------------------------
#define STAGE_BYTES 36864               // A (128*144) + B (128*144)
#define SMEM_BYTES  (3 * STAGE_BYTES)   // 110592

__global__ void __launch_bounds__(256, 2) gemm_tc_kernel() {
    extern __shared__ char smem[];
    const uint32_t sb  = smem_u32(smem);
    const int tid  = threadIdx.x;
    const int lane = tid & 31;
    const int wid  = tid >> 5;
    const int wm   = wid & 3;           // 0..3  (M)
    const int wn   = wid >> 2;          // 0..1  (N)
    const int nb    = blockIdx.x * 128; // 0..511 col base in [W1_l ; W1_r]
    const int mbase = blockIdx.y * 128;

    auto issue = [&](int s, int buf) {
        const int kb = s * 64;
        const uint32_t abase = sb + buf * STAGE_BYTES;
        const uint32_t bbase = abase + 18432;
#pragma unroll
        for (int j = 0; j < 4; j++) {
            int id  = tid + j * 256;
            int row = id >> 3, c = id & 7;
            cp16(abase + row * 144 + c * 16, g_A + (size_t)(mbase + row) * D_IN + kb + c * 8);
            cp16(bbase + row * 144 + c * 16, g_B + (size_t)(nb  + row) * D_IN + kb + c * 8);
        }
        cp_commit();
    };

    float d[2][8][4];
#pragma unroll
    for (int mt = 0; mt < 2; mt++)
#pragma unroll
        for (int nt = 0; nt < 8; nt++)
#pragma unroll
            for (int q = 0; q < 4; q++) d[mt][nt][q] = 0.f;

    issue(0, 0);
    issue(1, 1);

    const int arow = lane & 15, ahalf = lane >> 4;
    const int brow = (lane & 7) + ((lane >> 4) & 1) * 8, bhalf = (lane >> 3) & 1;

    for (int s = 0; s < KSTEPS; s++) {
        if (s == KSTEPS - 1) cp_wait<0>(); else cp_wait<1>();
        __syncthreads();
        if (s + 2 < KSTEPS) issue(s + 2, (s + 2) % 3);

        const int buf = s % 3;
        const uint32_t abase = sb + buf * STAGE_BYTES + (wm * 32) * 144;
        const uint32_t bbase = sb + buf * STAGE_BYTES + 18432 + (wn * 64) * 144;

#pragma unroll
        for (int kk = 0; kk < 4; kk++) {
            uint32_t ar[2][4];
#pragma unroll
            for (int mt = 0; mt < 2; mt++)
                ldm_x4(ar[mt], abase + (mt * 16 + arow) * 144 + kk * 32 + ahalf * 16);
            uint32_t br[4][4];
#pragma unroll
            for (int bt = 0; bt < 4; bt++)
                ldm_x4(br[bt], bbase + (bt * 16 + brow) * 144 + kk * 32 + bhalf * 16);
#pragma unroll
            for (int mt = 0; mt < 2; mt++)
#pragma unroll
                for (int nt = 0; nt < 8; nt++)
                    mma16816(d[mt][nt], ar[mt], br[nt >> 1][(nt & 1) * 2],
                             br[nt >> 1][(nt & 1) * 2 + 1]);
        }
    }

    // epilogue: blocks 0,1 write fp16 y_l; blocks 2,3 write fp32 y_r
    const bool is_l = (blockIdx.x < 2);
#pragma unroll
    for (int mt = 0; mt < 2; mt++) {
        int row = mbase + wm * 32 + mt * 16 + (lane >> 2);
#pragma unroll
        for (int nt = 0; nt < 8; nt++) {
            int col = nb + wn * 64 + nt * 8 + (lane & 3) * 2;   // 0..511
            if (is_l) {
                __half2 p0 = __floats2half2_rn(d[mt][nt][0], d[mt][nt][1]);
                __half2 p1 = __floats2half2_rn(d[mt][nt][2], d[mt][nt][3]);
                if (row < N_NODES)
                    *reinterpret_cast<__half2*>(g_yl + (size_t)row * 256 + col) = p0;
                if (row + 8 < N_NODES)
                    *reinterpret_cast<__half2*>(g_yl + (size_t)(row + 8) * 256 + col) = p1;
            } else {
                int c2 = col - 256;
                if (row < N_NODES)
                    *reinterpret_cast<float2*>(g_yr + (size_t)row * 256 + c2) =
                        make_float2(d[mt][nt][0], d[mt][nt][1]);
                if (row + 8 < N_NODES)
                    *reinterpret_cast<float2*>(g_yr + (size_t)(row + 8) * 256 + c2) =
                        make_float2(d[mt][nt][2], d[mt][nt][3]);
            }
        }
    }
}

// ---------------------------------------------------------------------------
// edge scatter of y_l (fp16 gather -> fp32 vector reductions) + degree count
// ---------------------------------------------------------------------------
__global__ void scatter1_kernel(const int* __restrict__ ei) {
    int t = blockIdx.x * 256 + threadIdx.x;
    int e = t >> 6;
    int c = t & 63;
    if (e >= N_EDGES) return;
    int src = ei[e];
    int dst = ei[N_EDGES + e];
    uint2 hv = *reinterpret_cast<const uint2*>(g_yl + (size_t)src * 256 + c * 4);
    float2 f0 = __half22float2(*reinterpret_cast<__half2*>(&hv.x));
    float2 f1 = __half22float2(*reinterpret_cast<__half2*>(&hv.y));
    float* p = g_agg1 + (size_t)dst * 256 + c * 4;
    asm volatile("red.global.add.v4.f32 [%0], {%1,%2,%3,%4};"
                 :: "l"(p), "f"(f0.x), "f"(f0.y), "f"(f1.x), "f"(f1.y) : "memory");
    if (c == 0) atomicAdd(g_cnt + dst, 1.0f);
}

// ---------------------------------------------------------------------------
// h = relu(agg1/max(cnt,1) + y_r + b1)
// ---------------------------------------------------------------------------
__global__ void hidden_kernel(const float* __restrict__ b1) {
    int t = blockIdx.x * 256 + threadIdx.x;
    if (t >= N_NODES * 64) return;
    int i = t >> 6, c = t & 63;
    float inv = 1.0f / fmaxf(g_cnt[i], 1.0f);
    float4 a  = *reinterpret_cast<const float4*>(g_agg1 + (size_t)i * 256 + c * 4);
    float4 yr = *reinterpret_cast<const float4*>(g_yr + (size_t)i * 256 + c * 4);
    float4 bb = *reinterpret_cast<const float4*>(b1 + c * 4);
    float4 o;
    o.x = fmaxf(fmaf(a.x, inv, yr.x + bb.x), 0.f);
    o.y = fmaxf(fmaf(a.y, inv, yr.y + bb.y), 0.f);
    o.z = fmaxf(fmaf(a.z, inv, yr.z + bb.z), 0.f);
    o.w = fmaxf(fmaf(a.w, inv, yr.w + bb.w), 0.f);
    *reinterpret_cast<float4*>(g_h + (size_t)i * 256 + c * 4) = o;
}

// ---------------------------------------------------------------------------
// layer-2 projection per node (warp per node)
// ---------------------------------------------------------------------------
__global__ void __launch_bounds__(256) layer2_kernel(
    const float* __restrict__ W2l, const float* __restrict__ W2r)
{
    __shared__ float w[4][256];
    int tid = threadIdx.x;
    float* ws = &w[0][0];
#pragma unroll
    for (int j = 0; j < 4; j++) {
        int idx = tid + j * 256;
        ws[idx] = (idx < 512) ? W2l[idx] : W2r[idx - 512];
    }
    __syncthreads();
    int warp = tid >> 5, lane = tid & 31;
    int node = blockIdx.x * 8 + warp;
    if (node >= N_NODES) return;
    float a0 = 0.f, a1 = 0.f, a2 = 0.f, a3 = 0.f;
    const float* hp = g_h + (size_t)node * 256;
#pragma unroll
    for (int j = 0; j < 8; j++) {
        int c = j * 32 + lane;
        float hv = hp[c];
        a0 = fmaf(hv, w[0][c], a0);
        a1 = fmaf(hv, w[1][c], a1);
        a2 = fmaf(hv, w[2][c], a2);
        a3 = fmaf(hv, w[3][c], a3);
    }
#pragma unroll
    for (int s = 16; s > 0; s >>= 1) {
        a0 += __shfl_xor_sync(0xFFFFFFFFu, a0, s);
        a1 += __shfl_xor_sync(0xFFFFFFFFu, a1, s);
        a2 += __shfl_xor_sync(0xFFFFFFFFu, a2, s);
        a3 += __shfl_xor_sync(0xFFFFFFFFu, a3, s);
    }
    if (lane == 0)
        *reinterpret_cast<float4*>(g_z + (size_t)node * 4) = make_float4(a0, a1, a2, a3);
}

__global__ void scatter2_kernel(const int* __restrict__ ei) {
    int e = blockIdx.x * 256 + threadIdx.x;
    if (e >= N_EDGES) return;
    int src = ei[e];
    int dst = ei[N_EDGES + e];
    atomicAdd(g_agg2 + (size_t)dst * 2 + 0, g_z[(size_t)src * 4 + 0]);
    atomicAdd(g_agg2 + (size_t)dst * 2 + 1, g_z[(size_t)src * 4 + 1]);
}

__global__ void final_kernel(const float* __restrict__ b2, float* __restrict__ out) {
    int i = blockIdx.x * 256 + threadIdx.x;
    if (i >= N_NODES) return;
    float inv = 1.0f / fmaxf(g_cnt[i], 1.0f);
    out[(size_t)i * 2 + 0] = fmaf(g_agg2[(size_t)i * 2 + 0], inv, g_z[(size_t)i * 4 + 2] + b2[0]);
    out[(size_t)i * 2 + 1] = fmaf(g_agg2[(size_t)i * 2 + 1], inv, g_z[(size_t)i * 4 + 3] + b2[1]);
}

extern "C" void kernel_launch(void* const* d_in, const int* in_sizes, int n_in,
                              void* d_out, int out_size) {
    const float* x    = (const float*)d_in[0];
    const int*   ei   = (const int*)d_in[1];
    const float* W1l  = (const float*)d_in[2];
    const float* b1   = (const float*)d_in[3];
    const float* W1r  = (const float*)d_in[4];
    const float* W2l  = (const float*)d_in[5];
    const float* b2   = (const float*)d_in[6];
    const float* W2r  = (const float*)d_in[7];
    float*       out  = (float*)d_out;

    static bool attr_set = false;
    if (!attr_set) {
        cudaFuncSetAttribute(gemm_tc_kernel,
                             cudaFuncAttributeMaxDynamicSharedMemorySize, SMEM_BYTES);
        attr_set = true;
    }

    conv_x_kernel<<<(N_NODES * (D_IN / 4) + 255) / 256, 256>>>(x);
    conv_w_kernel<<<(512 * D_IN + 255) / 256, 256>>>(W1l, W1r);

    dim3 gg(4, M_PAD / 128);
    gemm_tc_kernel<<<gg, 256, SMEM_BYTES>>>();

    scatter1_kernel<<<(N_EDGES * 64 + 255) / 256, 256>>>(ei);
    hidden_kernel<<<(N_NODES * 64 + 255) / 256, 256>>>(b1);
    layer2_kernel<<<(N_NODES + 7) / 8, 256>>>(W2l, W2r);
    scatter2_kernel<<<(N_EDGES + 255) / 256, 256>>>(ei);
    final_kernel<<<(N_NODES + 255) / 256, 256>>>(b2, out);
}

// round 8
// speedup vs baseline: 4.6713x; 1.1772x over previous
#include <cuda_runtime.h>
#include <cuda_fp16.h>
#include <cstdint>

#define N_NODES 50000
#define N_EDGES 250000
#define D_IN    768
#define D_HID   256

#define M_PAD   50048           // 391 * 128
#define KSTEPS  12              // 768 / 64
#define SCAN_BLOCKS 196         // ceil(50000/256)

__device__ __half g_yl[(size_t)N_NODES * 256];  // y_l = x@W1_l^T  (fp16)
__device__ float  g_yr[(size_t)N_NODES * 256];  // y_r = x@W1_r^T  (fp32)
__device__ float  g_z[(size_t)N_NODES * 4];     // zl0,zl1,zr0,zr1
__device__ __half g_A[(size_t)M_PAD * D_IN];    // x fp16; padded rows stay 0
__device__ __half g_B[(size_t)512 * D_IN];      // rows 0..255 = W1_l, 256..511 = W1_r
__device__ int    g_deg[N_NODES];
__device__ int    g_off[N_NODES];
__device__ int    g_pos[N_NODES];
__device__ int    g_srcs[N_EDGES];
__device__ int    g_bsum[SCAN_BLOCKS];
__device__ int    g_bscan[SCAN_BLOCKS];

// ---------------------------------------------------------------------------
// helpers
// ---------------------------------------------------------------------------
__device__ __forceinline__ uint32_t smem_u32(const void* p) {
    uint32_t a;
    asm("{ .reg .u64 t; cvta.to.shared.u64 t, %1; cvt.u32.u64 %0, t; }" : "=r"(a) : "l"(p));
    return a;
}
__device__ __forceinline__ void cp16(uint32_t dst, const void* src) {
    asm volatile("cp.async.cg.shared.global [%0], [%1], 16;" :: "r"(dst), "l"(src));
}
__device__ __forceinline__ void cp_commit() { asm volatile("cp.async.commit_group;" ::: "memory"); }
template <int N> __device__ __forceinline__ void cp_wait() {
    asm volatile("cp.async.wait_group %0;" :: "n"(N) : "memory");
}
__device__ __forceinline__ void ldm_x4(uint32_t* r, uint32_t addr) {
    asm volatile("ldmatrix.sync.aligned.m8n8.x4.shared.b16 {%0,%1,%2,%3}, [%4];"
                 : "=r"(r[0]), "=r"(r[1]), "=r"(r[2]), "=r"(r[3]) : "r"(addr));
}
__device__ __forceinline__ void mma16816(float* d, const uint32_t* a, uint32_t b0, uint32_t b1) {
    asm volatile(
        "mma.sync.aligned.m16n8k16.row.col.f32.f16.f16.f32 "
        "{%0,%1,%2,%3}, {%4,%5,%6,%7}, {%8,%9}, {%0,%1,%2,%3};"
        : "+f"(d[0]), "+f"(d[1]), "+f"(d[2]), "+f"(d[3])
        : "r"(a[0]), "r"(a[1]), "r"(a[2]), "r"(a[3]), "r"(b0), "r"(b1));
}

// ---------------------------------------------------------------------------
// convert x -> fp16; zero degree histogram
// ---------------------------------------------------------------------------
__global__ void conv_x_kernel(const float* __restrict__ x) {
    int t = blockIdx.x * 256 + threadIdx.x;
    if (t < N_NODES) g_deg[t] = 0;
    if (t >= N_NODES * (D_IN / 4)) return;
    int m = t / (D_IN / 4), c4 = t % (D_IN / 4);
    float4 v = *reinterpret_cast<const float4*>(x + (size_t)m * D_IN + c4 * 4);
    __half2 h0 = __floats2half2_rn(v.x, v.y);
    __half2 h1 = __floats2half2_rn(v.z, v.w);
    *reinterpret_cast<uint2*>(g_A + (size_t)m * D_IN + c4 * 4) =
        make_uint2(*reinterpret_cast<uint32_t*>(&h0), *reinterpret_cast<uint32_t*>(&h1));
}

// ---------------------------------------------------------------------------
// convert W1 -> fp16; also histogram dst degrees (runs after conv_x zeroed it)
// ---------------------------------------------------------------------------
__global__ void conv_w_kernel(const float* __restrict__ Wl, const float* __restrict__ Wr,
                              const int* __restrict__ ei) {
    int t = blockIdx.x * 256 + threadIdx.x;
    if (t < N_EDGES) atomicAdd(&g_deg[ei[N_EDGES + t]], 1);
    if (t >= 512 * D_IN) return;
    int r = t / D_IN, c = t % D_IN;
    float v = (r < 256) ? Wl[(size_t)r * D_IN + c] : Wr[(size_t)(r - 256) * D_IN + c];
    g_B[(size_t)r * D_IN + c] = __float2half_rn(v);
}

// ---------------------------------------------------------------------------
// exclusive scan of g_deg -> g_off (3 passes)
// ---------------------------------------------------------------------------
__global__ void scan_a_kernel() {
    __shared__ int s[256];
    int tid = threadIdx.x, t = blockIdx.x * 256 + tid;
    int val = (t < N_NODES) ? g_deg[t] : 0;
    s[tid] = val; __syncthreads();
#pragma unroll
    for (int o = 1; o < 256; o <<= 1) {
        int v = (tid >= o) ? s[tid - o] : 0;
        __syncthreads();
        s[tid] += v;
        __syncthreads();
    }
    if (t < N_NODES) g_off[t] = s[tid] - val;
    if (tid == 255) g_bsum[blockIdx.x] = s[255];
}
__global__ void scan_b_kernel() {
    __shared__ int s[256];
    int tid = threadIdx.x;
    int val = (tid < SCAN_BLOCKS) ? g_bsum[tid] : 0;
    s[tid] = val; __syncthreads();
#pragma unroll
    for (int o = 1; o < 256; o <<= 1) {
        int v = (tid >= o) ? s[tid - o] : 0;
        __syncthreads();
        s[tid] += v;
        __syncthreads();
    }
    if (tid < SCAN_BLOCKS) g_bscan[tid] = s[tid] - val;
}
__global__ void scan_c_kernel() {
    int t = blockIdx.x * 256 + threadIdx.x;
    if (t >= N_NODES) return;
    int o = g_off[t] + g_bscan[t >> 8];
    g_off[t] = o;
    g_pos[t] = o;
}

// ---------------------------------------------------------------------------
// counting sort: bucket src ids by dst
// ---------------------------------------------------------------------------
__global__ void sort_kernel(const int* __restrict__ ei) {
    int e = blockIdx.x * 256 + threadIdx.x;
    if (e >= N_EDGES) return;
    int dst = ei[N_EDGES + e];
    int p = atomicAdd(&g_pos[dst], 1);
    g_srcs[p] = ei[e];
}

// ---------------------------------------------------------------------------
// tensor-core GEMM (mma.sync fp16), K=768
// 128x128 tile, BK=64, 8 warps (4M x 2N), 3-stage cp.async
// blockIdx.x: 0,1 -> y_l (fp16 out), 2,3 -> y_r (fp32 out)
// ---------------------------------------------------------------------------
#define STAGE_BYTES 36864
#define SMEM_BYTES  (3 * STAGE_BYTES)

__global__ void __launch_bounds__(256, 2) gemm_tc_kernel() {
    extern __shared__ char smem[];
    const uint32_t sb  = smem_u32(smem);
    const int tid  = threadIdx.x;
    const int lane = tid & 31;
    const int wid  = tid >> 5;
    const int wm   = wid & 3;
    const int wn   = wid >> 2;
    const int nb    = blockIdx.x * 128;
    const int mbase = blockIdx.y * 128;

    auto issue = [&](int s, int buf) {
        const int kb = s * 64;
        const uint32_t abase = sb + buf * STAGE_BYTES;
        const uint32_t bbase = abase + 18432;
#pragma unroll
        for (int j = 0; j < 4; j++) {
            int id  = tid + j * 256;
            int row = id >> 3, c = id & 7;
            cp16(abase + row * 144 + c * 16, g_A + (size_t)(mbase + row) * D_IN + kb + c * 8);
            cp16(bbase + row * 144 + c * 16, g_B + (size_t)(nb  + row) * D_IN + kb + c * 8);
        }
        cp_commit();
    };

    float d[2][8][4];
#pragma unroll
    for (int mt = 0; mt < 2; mt++)
#pragma unroll
        for (int nt = 0; nt < 8; nt++)
#pragma unroll
            for (int q = 0; q < 4; q++) d[mt][nt][q] = 0.f;

    issue(0, 0);
    issue(1, 1);

    const int arow = lane & 15, ahalf = lane >> 4;
    const int brow = (lane & 7) + ((lane >> 4) & 1) * 8, bhalf = (lane >> 3) & 1;

    for (int s = 0; s < KSTEPS; s++) {
        if (s == KSTEPS - 1) cp_wait<0>(); else cp_wait<1>();
        __syncthreads();
        if (s + 2 < KSTEPS) issue(s + 2, (s + 2) % 3);

        const int buf = s % 3;
        const uint32_t abase = sb + buf * STAGE_BYTES + (wm * 32) * 144;
        const uint32_t bbase = sb + buf * STAGE_BYTES + 18432 + (wn * 64) * 144;

#pragma unroll
        for (int kk = 0; kk < 4; kk++) {
            uint32_t ar[2][4];
#pragma unroll
            for (int mt = 0; mt < 2; mt++)
                ldm_x4(ar[mt], abase + (mt * 16 + arow) * 144 + kk * 32 + ahalf * 16);
            uint32_t br[4][4];
#pragma unroll
            for (int bt = 0; bt < 4; bt++)
                ldm_x4(br[bt], bbase + (bt * 16 + brow) * 144 + kk * 32 + bhalf * 16);
#pragma unroll
            for (int mt = 0; mt < 2; mt++)
#pragma unroll
                for (int nt = 0; nt < 8; nt++)
                    mma16816(d[mt][nt], ar[mt], br[nt >> 1][(nt & 1) * 2],
                             br[nt >> 1][(nt & 1) * 2 + 1]);
        }
    }

    const bool is_l = (blockIdx.x < 2);
#pragma unroll
    for (int mt = 0; mt < 2; mt++) {
        int row = mbase + wm * 32 + mt * 16 + (lane >> 2);
#pragma unroll
        for (int nt = 0; nt < 8; nt++) {
            int col = nb + wn * 64 + nt * 8 + (lane & 3) * 2;
            if (is_l) {
                __half2 p0 = __floats2half2_rn(d[mt][nt][0], d[mt][nt][1]);
                __half2 p1 = __floats2half2_rn(d[mt][nt][2], d[mt][nt][3]);
                if (row < N_NODES)
                    *reinterpret_cast<__half2*>(g_yl + (size_t)row * 256 + col) = p0;
                if (row + 8 < N_NODES)
                    *reinterpret_cast<__half2*>(g_yl + (size_t)(row + 8) * 256 + col) = p1;
            } else {
                int c2 = col - 256;
                if (row < N_NODES)
                    *reinterpret_cast<float2*>(g_yr + (size_t)row * 256 + c2) =
                        make_float2(d[mt][nt][0], d[mt][nt][1]);
                if (row + 8 < N_NODES)
                    *reinterpret_cast<float2*>(g_yr + (size_t)(row + 8) * 256 + c2) =
                        make_float2(d[mt][nt][2], d[mt][nt][3]);
            }
        }
    }
}

// ---------------------------------------------------------------------------
// fused aggregation + hidden + layer-2 projection.
// warp per node (grid-stride over contiguous chunks). Per-lane dims: lane*8..+7.
// Per-lane register copies of W2 (4x8) and b1 (8).
// ---------------------------------------------------------------------------
#define AGG_BLOCKS 296
#define AGG_WARPS  (AGG_BLOCKS * 8)      // 2368
#define NODES_PER_WARP ((N_NODES + AGG_WARPS - 1) / AGG_WARPS)   // 22

__global__ void __launch_bounds__(256) agg_fused_kernel(
    const float* __restrict__ b1,
    const float* __restrict__ W2l, const float* __restrict__ W2r)
{
    int tid = threadIdx.x, lane = tid & 31;
    int gwarp = blockIdx.x * 8 + (tid >> 5);
    int node0 = gwarp * NODES_PER_WARP;
    if (node0 >= N_NODES) return;
    int node1 = min(node0 + NODES_PER_WARP, N_NODES);

    // per-lane weights/bias for dims lane*8 .. lane*8+7
    float wr[4][8], b1r[8];
    {
        const float* base = b1 + lane * 8;
        *reinterpret_cast<float4*>(&b1r[0]) = *reinterpret_cast<const float4*>(base);
        *reinterpret_cast<float4*>(&b1r[4]) = *reinterpret_cast<const float4*>(base + 4);
#pragma unroll
        for (int k = 0; k < 2; k++) {
            const float* wl = W2l + k * 256 + lane * 8;
            const float* wrp = W2r + k * 256 + lane * 8;
            *reinterpret_cast<float4*>(&wr[k][0])     = *reinterpret_cast<const float4*>(wl);
            *reinterpret_cast<float4*>(&wr[k][4])     = *reinterpret_cast<const float4*>(wl + 4);
            *reinterpret_cast<float4*>(&wr[k + 2][0]) = *reinterpret_cast<const float4*>(wrp);
            *reinterpret_cast<float4*>(&wr[k + 2][4]) = *reinterpret_cast<const float4*>(wrp + 4);
        }
    }

    for (int node = node0; node < node1; node++) {
        int off = g_off[node], deg = g_deg[node];
        float acc[8];
#pragma unroll
        for (int j = 0; j < 8; j++) acc[j] = 0.f;

        for (int e = 0; e < deg; e++) {
            int src = g_srcs[off + e];
            uint4 v = *reinterpret_cast<const uint4*>(g_yl + (size_t)src * 256 + lane * 8);
            const __half2* hp = reinterpret_cast<const __half2*>(&v);
#pragma unroll
            for (int q = 0; q < 4; q++) {
                float2 f = __half22float2(hp[q]);
                acc[q * 2]     += f.x;
                acc[q * 2 + 1] += f.y;
            }
        }

        float inv = 1.0f / fmaxf((float)deg, 1.0f);
        const float* yrp = g_yr + (size_t)node * 256 + lane * 8;
        float4 y0 = *reinterpret_cast<const float4*>(yrp);
        float4 y1 = *reinterpret_cast<const float4*>(yrp + 4);
        float yv[8] = {y0.x, y0.y, y0.z, y0.w, y1.x, y1.y, y1.z, y1.w};

        float a0 = 0.f, a1 = 0.f, a2 = 0.f, a3 = 0.f;
#pragma unroll
        for (int j = 0; j < 8; j++) {
            float h = fmaxf(fmaf(acc[j], inv, yv[j] + b1r[j]), 0.f);
            a0 = fmaf(h, wr[0][j], a0);
            a1 = fmaf(h, wr[1][j], a1);
            a2 = fmaf(h, wr[2][j], a2);
            a3 = fmaf(h, wr[3][j], a3);
        }
#pragma unroll
        for (int s = 16; s > 0; s >>= 1) {
            a0 += __shfl_xor_sync(0xFFFFFFFFu, a0, s);
            a1 += __shfl_xor_sync(0xFFFFFFFFu, a1, s);
            a2 += __shfl_xor_sync(0xFFFFFFFFu, a2, s);
            a3 += __shfl_xor_sync(0xFFFFFFFFu, a3, s);
        }
        if (lane == 0)
            *reinterpret_cast<float4*>(g_z + (size_t)node * 4) = make_float4(a0, a1, a2, a3);
    }
}

// ---------------------------------------------------------------------------
// fused layer-2 aggregation + output (thread per node, CSR gather, no atomics)
// ---------------------------------------------------------------------------
__global__ void final_kernel(const float* __restrict__ b2, float* __restrict__ out) {
    int i = blockIdx.x * 256 + threadIdx.x;
    if (i >= N_NODES) return;
    int off = g_off[i], deg = g_deg[i];
    float s0 = 0.f, s1 = 0.f;
    for (int e = 0; e < deg; e++) {
        int src = g_srcs[off + e];
        float2 zl = *reinterpret_cast<const float2*>(g_z + (size_t)src * 4);
        s0 += zl.x; s1 += zl.y;
    }
    float inv = 1.0f / fmaxf((float)deg, 1.0f);
    float2 zr = *reinterpret_cast<const float2*>(g_z + (size_t)i * 4 + 2);
    out[(size_t)i * 2 + 0] = fmaf(s0, inv, zr.x + b2[0]);
    out[(size_t)i * 2 + 1] = fmaf(s1, inv, zr.y + b2[1]);
}

extern "C" void kernel_launch(void* const* d_in, const int* in_sizes, int n_in,
                              void* d_out, int out_size) {
    const float* x    = (const float*)d_in[0];
    const int*   ei   = (const int*)d_in[1];
    const float* W1l  = (const float*)d_in[2];
    const float* b1   = (const float*)d_in[3];
    const float* W1r  = (const float*)d_in[4];
    const float* W2l  = (const float*)d_in[5];
    const float* b2   = (const float*)d_in[6];
    const float* W2r  = (const float*)d_in[7];
    float*       out  = (float*)d_out;

    static bool attr_set = false;
    if (!attr_set) {
        cudaFuncSetAttribute(gemm_tc_kernel,
                             cudaFuncAttributeMaxDynamicSharedMemorySize, SMEM_BYTES);
        attr_set = true;
    }

    conv_x_kernel<<<(N_NODES * (D_IN / 4) + 255) / 256, 256>>>(x);
    conv_w_kernel<<<(512 * D_IN + 255) / 256, 256>>>(W1l, W1r, ei);

    scan_a_kernel<<<SCAN_BLOCKS, 256>>>();
    scan_b_kernel<<<1, 256>>>();
    scan_c_kernel<<<SCAN_BLOCKS, 256>>>();
    sort_kernel<<<(N_EDGES + 255) / 256, 256>>>(ei);

    dim3 gg(4, M_PAD / 128);
    gemm_tc_kernel<<<gg, 256, SMEM_BYTES>>>();

    agg_fused_kernel<<<AGG_BLOCKS, 256>>>(b1, W2l, W2r);
    final_kernel<<<(N_NODES + 255) / 256, 256>>>(b2, out);
}